// round 16
// baseline (speedup 1.0000x reference)
#include <cuda_runtime.h>
#include <cstdint>

// Proposal_Sampling: B=32, T=64, D=512, K=80
// 4 independent blocks per batch; each REDUNDANTLY selects top-80 of the full 4096
// logits, then writes its quarter (20 proposals). No inter-block sync.
// R16: BALLOT coarse-count (32 value regions, zero LSU) replaces the 4096-key atomic
// histogram; only the ~200 boundary-superset keys are compacted and full-key ranked.
// Exact fallback (R15 fine histogram) if candidates would overflow (never for bench data).
// Output flat f32: prop_lists[32,80,512] | pred_s_e[32,80,2] | offset_gt_list[32,80,2] | pred_score[32,80]

#define BATCH 32
#define TDIM  64
#define TT    4096
#define DDIM  512
#define KSEL  80
#define NT    512
#define KPT   8
#define NB    4096                 // fine value-domain bins (fallback only)
#define BPT   (NB / NT)
#define PADB(d) ((d) + ((d) >> 3))
#define NBP   (NB + (NB >> 3))     // 4608 ints
#define CCAP  512                  // candidate capacity (uniform input uses ~200)
#define QSEL  20
#define NBLK  (BATCH * 4)          // 128 blocks <= 148 SMs

__global__ __launch_bounds__(NT, 1)
void proposal_kernel(const float* __restrict__ logit,
                     const float* __restrict__ map2d,
                     const float* __restrict__ offset_gt,
                     const float* __restrict__ tmap,
                     float* __restrict__ out)
{
    __shared__ int wcnt[16 * 32];                  // per-warp 32-region counts
    __shared__ int whist[NBP];                     // fallback fine histogram (18 KB)
    __shared__ int warp_part[16];
    __shared__ int sh_r, sh_cc, sh_cnt;
    __shared__ unsigned long long cand[CCAP];
    __shared__ int sh_idx[QSEL];

    const int tid  = threadIdx.x;
    const int lane = tid & 31;
    const int wid  = tid >> 5;
    const int b    = blockIdx.x >> 2;              // batch
    const int q    = blockIdx.x & 3;               // quarter: ranks [q*20, q*20+20)

    float* prop = out;
    float* pse  = out + (size_t)BATCH * KSEL * DDIM;
    float* ofl  = pse + (size_t)BATCH * KSEL * 2;
    float* psc  = ofl + (size_t)BATCH * KSEL * 2;

    // ---- load logits, build keys + fine value bins (coarse region = fine >> 7) ----
    // key = (monotone score bits << 12) | (4095 - idx); zero logit -> key 0 (-inf mask)
    // fine bin = clamp((int)(v*4096), 0, 4095): monotone in v => monotone vs key order
    const float4* lg4 = (const float4*)(logit + (size_t)b * TT);
    unsigned long long karr[KPT];
    int barr[KPT];
    {
        float4 a = lg4[tid * 2 + 0];
        float4 c = lg4[tid * 2 + 1];
        float vs[KPT] = {a.x, a.y, a.z, a.w, c.x, c.y, c.z, c.w};
        #pragma unroll
        for (int j = 0; j < KPT; j++) {
            int i = tid * KPT + j;
            float v = vs[j];
            unsigned u;
            if (v == 0.0f) u = 0u;
            else {
                unsigned bits = __float_as_uint(v);
                u = (bits & 0x80000000u) ? ~bits : (bits | 0x80000000u);
            }
            karr[j] = ((unsigned long long)u << 12) | (unsigned)(TT - 1 - i);
            int bb = (int)(v * (float)NB);
            barr[j] = (bb < 0) ? 0 : ((bb > NB - 1) ? NB - 1 : bb);
        }
    }
    if (tid == 0) sh_cnt = 0;

    // ---- coarse count: 32 value regions via ballots (registers only, no atomics) ----
    {
        int cnt = 0;
        #pragma unroll
        for (int j = 0; j < KPT; j++) {
            int r = barr[j] >> 7;                  // region 0..31
            unsigned b0 = __ballot_sync(0xffffffffu, r & 1);
            unsigned b1 = __ballot_sync(0xffffffffu, r & 2);
            unsigned b2 = __ballot_sync(0xffffffffu, r & 4);
            unsigned b3 = __ballot_sync(0xffffffffu, r & 8);
            unsigned b4 = __ballot_sync(0xffffffffu, r & 16);
            unsigned m = (lane & 1)  ? b0 : ~b0;
            m &= (lane & 2)  ? b1 : ~b1;
            m &= (lane & 4)  ? b2 : ~b2;
            m &= (lane & 8)  ? b3 : ~b3;
            m &= (lane & 16) ? b4 : ~b4;
            cnt += __popc(m);                      // lane L: count of this warp's keys in region L
        }
        wcnt[wid * 32 + lane] = cnt;
    }
    __syncthreads();

    // ---- warp 0: reduce 16 warps, suffix-scan 32 regions, pick cutoff region ----
    if (wid == 0) {
        int total = 0;
        #pragma unroll
        for (int w = 0; w < 16; w++) total += wcnt[w * 32 + lane];
        int s = total;
        #pragma unroll
        for (int off = 1; off < 32; off <<= 1) {
            int o = __shfl_down_sync(0xffffffffu, s, off);
            if (lane + off < 32) s += o;
        }
        int gt = __shfl_down_sync(0xffffffffu, s, 1);
        if (lane == 31) gt = 0;
        if (s >= KSEL && gt < KSEL) { sh_r = lane; sh_cc = s; }  // unique winner
    }
    __syncthreads();

    if (sh_cc <= CCAP) {
        // ======== fast path: collect keys with region >= r* (exact top-80 superset) ========
        const int rstar = sh_r;
        #pragma unroll
        for (int j = 0; j < KPT; j++) {
            if ((barr[j] >> 7) >= rstar)
                cand[atomicAdd(&sh_cnt, 1)] = karr[j];   // ~200 atomics total (order irrelevant)
        }
    } else {
        // ======== exact fallback: R15 fine histogram + gt filter (never for bench data) ====
        #pragma unroll
        for (int d = tid; d < NBP; d += NT) whist[d] = 0;
        __syncthreads();
        #pragma unroll
        for (int j = 0; j < KPT; j++) atomicAdd(&whist[PADB(barr[j])], 1);
        __syncthreads();
        int val[BPT], suf[BPT];
        #pragma unroll
        for (int i = 0; i < BPT; i++) val[i] = whist[9 * tid + i];
        suf[BPT - 1] = val[BPT - 1];
        #pragma unroll
        for (int i = BPT - 2; i >= 0; i--) suf[i] = suf[i + 1] + val[i];
        int tot = suf[0];
        int s = tot;
        #pragma unroll
        for (int off = 1; off < 32; off <<= 1) {
            int o = __shfl_down_sync(0xffffffffu, s, off);
            if (lane + off < 32) s += o;
        }
        if (lane == 0) warp_part[wid] = s;
        __syncthreads();
        if (wid == 0) {
            int p = (lane < 16) ? warp_part[lane] : 0;
            int orig = p;
            #pragma unroll
            for (int off = 1; off < 16; off <<= 1) {
                int o = __shfl_down_sync(0xffffffffu, p, off);
                if (lane + off < 16) p += o;
            }
            if (lane < 16) warp_part[lane] = p - orig;
        }
        __syncthreads();
        {
            const int above = warp_part[wid] + (s - tot);
            #pragma unroll
            for (int i = 0; i < BPT; i++) whist[9 * tid + i] = above + suf[i] - val[i];
        }
        __syncthreads();
        #pragma unroll
        for (int j = 0; j < KPT; j++) {
            if (whist[PADB(barr[j])] < KSEL) {
                int p = atomicAdd(&sh_cnt, 1);
                if (p < CCAP) cand[p] = karr[j];
            }
        }
    }
    __syncthreads();
    const int cc = (sh_cnt < CCAP) ? sh_cnt : CCAP;

    // ---- rank candidates by full key: rank < 80 IS the exact global order ----
    const int r0 = q * QSEL;
    if (tid < cc) {
        unsigned long long mykey = cand[tid];
        int rank = 0;
        #pragma unroll 4
        for (int j = 0; j < cc; j++) rank += (cand[j] > mykey);
        if (rank >= r0 && rank < r0 + QSEL)
            sh_idx[rank - r0] = TT - 1 - (int)(mykey & 0xFFFull);
    }
    __syncthreads();

    // ---- gather: issue 5 big LDGs first, small outputs under their latency ----
    const int c  = tid & 127;          // float4 column
    const int p0 = tid >> 7;           // 0..3
    const int i0 = sh_idx[p0 +  0];
    const int i1 = sh_idx[p0 +  4];
    const int i2 = sh_idx[p0 +  8];
    const int i3 = sh_idx[p0 + 12];
    const int i4 = sh_idx[p0 + 16];
    const float4* s0 = (const float4*)(map2d + ((size_t)b * TT + i0) * DDIM);
    const float4* s1 = (const float4*)(map2d + ((size_t)b * TT + i1) * DDIM);
    const float4* s2 = (const float4*)(map2d + ((size_t)b * TT + i2) * DDIM);
    const float4* s3 = (const float4*)(map2d + ((size_t)b * TT + i3) * DDIM);
    const float4* s4 = (const float4*)(map2d + ((size_t)b * TT + i4) * DDIM);
    float4 v0 = s0[c];
    float4 v1 = s1[c];
    float4 v2 = s2[c];
    float4 v3 = s3[c];
    float4 v4 = s4[c];

    if (tid < QSEL) {                  // overlapped small outputs for this quarter
        int idx  = sh_idx[tid];
        int rank = r0 + tid;
        int row = idx >> 6;
        int col = idx & (TDIM - 1);
        const float* og = offset_gt + ((size_t)b * TT + idx) * 2;
        float og0 = og[0];
        float og1 = og[1];
        float tv  = tmap[(size_t)b * TT + idx];
        size_t o2 = ((size_t)b * KSEL + rank) * 2;
        pse[o2 + 0] = (float)row;
        pse[o2 + 1] = (float)(col + 1);
        ofl[o2 + 0] = og0;
        ofl[o2 + 1] = og1;
        psc[(size_t)b * KSEL + rank] = tv;
    }

    float4* d0 = (float4*)(prop + ((size_t)b * KSEL + r0 + p0 +  0) * DDIM);
    float4* d1 = (float4*)(prop + ((size_t)b * KSEL + r0 + p0 +  4) * DDIM);
    float4* d2 = (float4*)(prop + ((size_t)b * KSEL + r0 + p0 +  8) * DDIM);
    float4* d3 = (float4*)(prop + ((size_t)b * KSEL + r0 + p0 + 12) * DDIM);
    float4* d4 = (float4*)(prop + ((size_t)b * KSEL + r0 + p0 + 16) * DDIM);
    d0[c] = v0;
    d1[c] = v1;
    d2[c] = v2;
    d3[c] = v3;
    d4[c] = v4;
}

extern "C" void kernel_launch(void* const* d_in, const int* in_sizes, int n_in,
                              void* d_out, int out_size) {
    const float* logit     = (const float*)d_in[0];
    const float* map2d     = (const float*)d_in[1];
    const float* offset_gt = (const float*)d_in[2];
    const float* tmap      = (const float*)d_in[3];
    float* out = (float*)d_out;
    proposal_kernel<<<NBLK, NT>>>(logit, map2d, offset_gt, tmap, out);
}

// round 17
// speedup vs baseline: 1.0030x; 1.0030x over previous
#include <cuda_runtime.h>
#include <cstdint>

// Proposal_Sampling: B=32, T=64, D=512, K=80
// 4 independent blocks per batch; each REDUNDANTLY selects top-80 of the full 4096
// logits, then writes its quarter (20 proposals). No inter-block sync.
// R17: value-threshold prefilter (v > 0.95 -> ~205 candidate superset, register compares
// + 1 warp-reduce) replaces histogram/scan in the common path. Exact R15 fine-histogram
// fallback if the prefilter yields < 80 candidates (correct for ALL inputs).
// Output flat f32: prop_lists[32,80,512] | pred_s_e[32,80,2] | offset_gt_list[32,80,2] | pred_score[32,80]

#define BATCH 32
#define TDIM  64
#define TT    4096
#define DDIM  512
#define KSEL  80
#define NT    512
#define KPT   8
#define NB    4096                 // fine value-domain bins (fallback only)
#define BPT   (NB / NT)
#define PADB(d) ((d) + ((d) >> 3))
#define NBP   (NB + (NB >> 3))     // 4608 ints
#define CCAP  512                  // candidate capacity (uniform input uses ~205)
#define QSEL  20
#define NBLK  (BATCH * 4)          // 128 blocks <= 148 SMs
#define TLO   0.95f                // prefilter threshold (E[count]=205 for U(0,1))

__global__ __launch_bounds__(NT, 1)
void proposal_kernel(const float* __restrict__ logit,
                     const float* __restrict__ map2d,
                     const float* __restrict__ offset_gt,
                     const float* __restrict__ tmap,
                     float* __restrict__ out)
{
    __shared__ int whist[NBP];                     // fallback fine histogram (18 KB)
    __shared__ int warp_part[16];
    __shared__ int sh_cc, sh_cnt;
    __shared__ unsigned long long cand[CCAP];
    __shared__ int sh_idx[QSEL];

    const int tid  = threadIdx.x;
    const int lane = tid & 31;
    const int wid  = tid >> 5;
    const int b    = blockIdx.x >> 2;              // batch
    const int q    = blockIdx.x & 3;               // quarter: ranks [q*20, q*20+20)

    float* prop = out;
    float* pse  = out + (size_t)BATCH * KSEL * DDIM;
    float* ofl  = pse + (size_t)BATCH * KSEL * 2;
    float* psc  = ofl + (size_t)BATCH * KSEL * 2;

    // ---- load logits, build keys; prefilter mask on v > TLO ----
    // key = (monotone score bits << 12) | (4095 - idx); zero logit -> key 0 (-inf mask)
    const float4* lg4 = (const float4*)(logit + (size_t)b * TT);
    unsigned long long karr[KPT];
    int barr[KPT];                                 // fine bins (fallback use)
    unsigned pmask = 0;
    {
        float4 a = lg4[tid * 2 + 0];
        float4 c = lg4[tid * 2 + 1];
        float vs[KPT] = {a.x, a.y, a.z, a.w, c.x, c.y, c.z, c.w};
        #pragma unroll
        for (int j = 0; j < KPT; j++) {
            int i = tid * KPT + j;
            float v = vs[j];
            unsigned u;
            if (v == 0.0f) u = 0u;
            else {
                unsigned bits = __float_as_uint(v);
                u = (bits & 0x80000000u) ? ~bits : (bits | 0x80000000u);
            }
            karr[j] = ((unsigned long long)u << 12) | (unsigned)(TT - 1 - i);
            int bb = (int)(v * (float)NB);
            barr[j] = (bb < 0) ? 0 : ((bb > NB - 1) ? NB - 1 : bb);
            if (v > TLO) pmask |= (1u << j);
        }
    }
    if (tid == 0) sh_cnt = 0;

    // ---- count survivors: register popc + warp reduce + tiny cross-warp reduce ----
    {
        int local = __popc(pmask);
        #pragma unroll
        for (int off = 16; off > 0; off >>= 1)
            local += __shfl_down_sync(0xffffffffu, local, off);
        if (lane == 0) warp_part[wid] = local;
    }
    __syncthreads();
    if (tid == 0) {
        int t = 0;
        #pragma unroll
        for (int w = 0; w < 16; w++) t += warp_part[w];
        sh_cc = t;
    }
    __syncthreads();

    if (sh_cc >= KSEL && sh_cc <= CCAP) {
        // ======== fast path: survivors are an exact top-80 superset ========
        #pragma unroll
        for (int j = 0; j < KPT; j++) {
            if ((pmask >> j) & 1u)
                cand[atomicAdd(&sh_cnt, 1)] = karr[j];   // ~205 aggregated atomics
        }
    } else {
        // ======== exact fallback: R15 fine histogram + gt filter ========
        #pragma unroll
        for (int d = tid; d < NBP; d += NT) whist[d] = 0;
        __syncthreads();
        #pragma unroll
        for (int j = 0; j < KPT; j++) atomicAdd(&whist[PADB(barr[j])], 1);
        __syncthreads();
        int val[BPT], suf[BPT];
        #pragma unroll
        for (int i = 0; i < BPT; i++) val[i] = whist[9 * tid + i];
        suf[BPT - 1] = val[BPT - 1];
        #pragma unroll
        for (int i = BPT - 2; i >= 0; i--) suf[i] = suf[i + 1] + val[i];
        int tot = suf[0];
        int s = tot;
        #pragma unroll
        for (int off = 1; off < 32; off <<= 1) {
            int o = __shfl_down_sync(0xffffffffu, s, off);
            if (lane + off < 32) s += o;
        }
        if (lane == 0) warp_part[wid] = s;
        __syncthreads();
        if (wid == 0) {
            int p = (lane < 16) ? warp_part[lane] : 0;
            int orig = p;
            #pragma unroll
            for (int off = 1; off < 16; off <<= 1) {
                int o = __shfl_down_sync(0xffffffffu, p, off);
                if (lane + off < 16) p += o;
            }
            if (lane < 16) warp_part[lane] = p - orig;
        }
        __syncthreads();
        {
            const int above = warp_part[wid] + (s - tot);
            #pragma unroll
            for (int i = 0; i < BPT; i++) whist[9 * tid + i] = above + suf[i] - val[i];
        }
        __syncthreads();
        #pragma unroll
        for (int j = 0; j < KPT; j++) {
            if (whist[PADB(barr[j])] < KSEL) {
                int p = atomicAdd(&sh_cnt, 1);
                if (p < CCAP) cand[p] = karr[j];
            }
        }
    }
    __syncthreads();
    const int cc = (sh_cnt < CCAP) ? sh_cnt : CCAP;

    // ---- rank candidates by full key: rank < 80 IS the exact global order ----
    const int r0 = q * QSEL;
    if (tid < cc) {
        unsigned long long mykey = cand[tid];
        int rank = 0;
        #pragma unroll 4
        for (int j = 0; j < cc; j++) rank += (cand[j] > mykey);
        if (rank >= r0 && rank < r0 + QSEL)
            sh_idx[rank - r0] = TT - 1 - (int)(mykey & 0xFFFull);
    }
    __syncthreads();

    // ---- gather: issue 5 big LDGs first, small outputs under their latency ----
    const int c  = tid & 127;          // float4 column
    const int p0 = tid >> 7;           // 0..3
    const int i0 = sh_idx[p0 +  0];
    const int i1 = sh_idx[p0 +  4];
    const int i2 = sh_idx[p0 +  8];
    const int i3 = sh_idx[p0 + 12];
    const int i4 = sh_idx[p0 + 16];
    const float4* s0 = (const float4*)(map2d + ((size_t)b * TT + i0) * DDIM);
    const float4* s1 = (const float4*)(map2d + ((size_t)b * TT + i1) * DDIM);
    const float4* s2 = (const float4*)(map2d + ((size_t)b * TT + i2) * DDIM);
    const float4* s3 = (const float4*)(map2d + ((size_t)b * TT + i3) * DDIM);
    const float4* s4 = (const float4*)(map2d + ((size_t)b * TT + i4) * DDIM);
    float4 v0 = s0[c];
    float4 v1 = s1[c];
    float4 v2 = s2[c];
    float4 v3 = s3[c];
    float4 v4 = s4[c];

    if (tid < QSEL) {                  // overlapped small outputs for this quarter
        int idx  = sh_idx[tid];
        int rank = r0 + tid;
        int row = idx >> 6;
        int col = idx & (TDIM - 1);
        const float* og = offset_gt + ((size_t)b * TT + idx) * 2;
        float og0 = og[0];
        float og1 = og[1];
        float tv  = tmap[(size_t)b * TT + idx];
        size_t o2 = ((size_t)b * KSEL + rank) * 2;
        pse[o2 + 0] = (float)row;
        pse[o2 + 1] = (float)(col + 1);
        ofl[o2 + 0] = og0;
        ofl[o2 + 1] = og1;
        psc[(size_t)b * KSEL + rank] = tv;
    }

    float4* d0 = (float4*)(prop + ((size_t)b * KSEL + r0 + p0 +  0) * DDIM);
    float4* d1 = (float4*)(prop + ((size_t)b * KSEL + r0 + p0 +  4) * DDIM);
    float4* d2 = (float4*)(prop + ((size_t)b * KSEL + r0 + p0 +  8) * DDIM);
    float4* d3 = (float4*)(prop + ((size_t)b * KSEL + r0 + p0 + 12) * DDIM);
    float4* d4 = (float4*)(prop + ((size_t)b * KSEL + r0 + p0 + 16) * DDIM);
    d0[c] = v0;
    d1[c] = v1;
    d2[c] = v2;
    d3[c] = v3;
    d4[c] = v4;
}

extern "C" void kernel_launch(void* const* d_in, const int* in_sizes, int n_in,
                              void* d_out, int out_size) {
    const float* logit     = (const float*)d_in[0];
    const float* map2d     = (const float*)d_in[1];
    const float* offset_gt = (const float*)d_in[2];
    const float* tmap      = (const float*)d_in[3];
    float* out = (float*)d_out;
    proposal_kernel<<<NBLK, NT>>>(logit, map2d, offset_gt, tmap, out);
}